// round 9
// baseline (speedup 1.0000x reference)
#include <cuda_runtime.h>
#include <cstdint>

#define S_LEN 2048
#define D_DIM 1024
#define NH    16
#define HDIM  64
#define NB    2
#define M_TOT 4096

// Scratch. Contraction dims pair-interleaved within aligned 8-blocks:
// new[2j] = old[j], new[2j+1] = old[j+4]  (fragment pairs adjacent -> LDS.64).
__device__ float g_q[NB * NH * S_LEN * HDIM];   // [b,h,s,hd] natural, 0.125-scaled
__device__ float g_k[NB * NH * S_LEN * HDIM];   // [b,h,s,hd~] hd-interleaved
__device__ float g_v[NB * NH * HDIM * S_LEN];   // [b,h,hd,s~] TRANSPOSED, s-interleaved
__device__ float g_ctx[NB * S_LEN * D_DIM];     // [b,s,d~] d-interleaved
__device__ float g_xc[M_TOT * D_DIM];           // [m,d~]
__device__ float g_wqc[D_DIM * D_DIM];          // [n,d~]
__device__ float g_wkc[D_DIM * D_DIM];
__device__ float g_wvc[D_DIM * D_DIM];
__device__ float g_woc[D_DIM * D_DIM];

// ---------------------------------------------------------------------------
__device__ __forceinline__ uint32_t f2tf(float f) {
    uint32_t u;
    asm("cvt.rna.tf32.f32 %0, %1;" : "=r"(u) : "f"(f));
    return u;
}
__device__ __forceinline__ float u2f(uint32_t u) { return __uint_as_float(u); }
__device__ __forceinline__ uint32_t fbits(float f) { return __float_as_uint(f); }
__device__ __forceinline__ int ilv8(int i) {        // old index -> interleaved pos
    return (i & ~7) | (((i & 3) << 1) | ((i >> 2) & 1));
}

__device__ __forceinline__ uint32_t smem_u32(const void* p) {
    uint32_t a;
    asm("{ .reg .u64 t; cvta.to.shared.u64 t, %1; cvt.u32.u64 %0, t; }" : "=r"(a) : "l"(p));
    return a;
}
__device__ __forceinline__ void mma_tf32(float d[4], const uint32_t a[4], const uint32_t b[2]) {
    asm("mma.sync.aligned.m16n8k8.row.col.f32.tf32.tf32.f32 "
        "{%0,%1,%2,%3}, {%4,%5,%6,%7}, {%8,%9}, {%0,%1,%2,%3};"
        : "+f"(d[0]), "+f"(d[1]), "+f"(d[2]), "+f"(d[3])
        : "r"(a[0]), "r"(a[1]), "r"(a[2]), "r"(a[3]), "r"(b[0]), "r"(b[1]));
}
__device__ __forceinline__ void cpa16(uint32_t dst, const void* src) {
    asm volatile("cp.async.ca.shared.global [%0], [%1], 16;" :: "r"(dst), "l"(src) : "memory");
}
__device__ __forceinline__ void cpa_commit() {
    asm volatile("cp.async.commit_group;" ::: "memory");
}
template <int N>
__device__ __forceinline__ void cpa_wait() {
    asm volatile("cp.async.wait_group %0;" :: "n"(N) : "memory");
}

// ---------------------------------------------------------------------------
// Prep: tf32-round + pair-interleave contraction dim of x and all weights.
// 8-float block {i0..i7} -> {i0,i4,i1,i5,i2,i6,i3,i7}.
// ---------------------------------------------------------------------------
__global__ __launch_bounds__(256) void prep_kernel(
    const float* __restrict__ x,  const float* __restrict__ wq,
    const float* __restrict__ wk, const float* __restrict__ wv,
    const float* __restrict__ wo)
{
    const float* src; float* dst; int n8;
    switch (blockIdx.y) {
        case 0: src = x;  dst = g_xc;  n8 = M_TOT * D_DIM / 8; break;
        case 1: src = wq; dst = g_wqc; n8 = D_DIM * D_DIM / 8; break;
        case 2: src = wk; dst = g_wkc; n8 = D_DIM * D_DIM / 8; break;
        case 3: src = wv; dst = g_wvc; n8 = D_DIM * D_DIM / 8; break;
        default: src = wo; dst = g_woc; n8 = D_DIM * D_DIM / 8; break;
    }
    const int stride = gridDim.x * blockDim.x;
    for (int i = blockIdx.x * blockDim.x + threadIdx.x; i < n8; i += stride) {
        float4 lo = __ldg((const float4*)src + 2 * i);
        float4 hi = __ldg((const float4*)src + 2 * i + 1);
        ((float4*)dst)[2 * i] = make_float4(u2f(f2tf(lo.x)), u2f(f2tf(hi.x)),
                                            u2f(f2tf(lo.y)), u2f(f2tf(hi.y)));
        ((float4*)dst)[2 * i + 1] = make_float4(u2f(f2tf(lo.z)), u2f(f2tf(hi.z)),
                                                u2f(f2tf(lo.w)), u2f(f2tf(hi.w)));
    }
}

// ---------------------------------------------------------------------------
// GEMM core: D[128,256] = A[128,1024~] @ B[256,1024~]^T  (interleaved k).
// 8 warps 2(m)x4(n), warp tile 64x64; 3-stage cp.async; all frags LDS.64.
// SMEM stride 40 (=8 mod 32) -> conflict-free per 16-lane phase.
// ---------------------------------------------------------------------------
#define GSA 5120                        // A stage floats (128*40)
#define GSB 10240                       // B stage floats (256*40)
#define GB_OFF (3 * GSA)
#define GEMM_SMEM ((3 * GSA + 3 * GSB) * 4)   // 184320 B

__device__ __forceinline__ void gemm_stage(
    uint32_t sbase, int buf, const float* __restrict__ Ag,
    const float* __restrict__ Bg, int ch)
{
    const int tid = threadIdx.x;
    #pragma unroll
    for (int t = 0; t < 4; t++) {
        int i = tid + t * 256, row = i >> 3, c4 = i & 7;
        cpa16(sbase + (buf * GSA + row * 40 + c4 * 4) * 4,
              Ag + (size_t)row * D_DIM + ch * 32 + c4 * 4);
    }
    #pragma unroll
    for (int t = 0; t < 8; t++) {
        int i = tid + t * 256, row = i >> 3, c4 = i & 7;
        cpa16(sbase + (GB_OFF + buf * GSB + row * 40 + c4 * 4) * 4,
              Bg + (size_t)row * D_DIM + ch * 32 + c4 * 4);
    }
    cpa_commit();
}

__device__ __forceinline__ void gemm128_core(
    const float* __restrict__ Ag, const float* __restrict__ Bg,
    float C[4][8][4], float* sm)
{
    const uint32_t sbase = smem_u32(sm);
    const int tid = threadIdx.x, wid = tid >> 5, lane = tid & 31;
    const int gq = lane >> 2, qi = lane & 3;
    const int wm = (wid >> 2) * 64, wn = (wid & 3) * 64;

    #pragma unroll
    for (int mi = 0; mi < 4; mi++)
        #pragma unroll
        for (int nt = 0; nt < 8; nt++)
            #pragma unroll
            for (int r = 0; r < 4; r++) C[mi][nt][r] = 0.f;

    gemm_stage(sbase, 0, Ag, Bg, 0);
    gemm_stage(sbase, 1, Ag, Bg, 1);

    int buf = 0, nbuf = 2;
    #pragma unroll 1
    for (int ch = 0; ch < 32; ch++) {
        if (ch == 31) cpa_wait<0>(); else cpa_wait<1>();
        __syncthreads();
        if (ch + 2 < 32) gemm_stage(sbase, nbuf, Ag, Bg, ch + 2);

        const float* as = sm + buf * GSA;
        const float* bs = sm + GB_OFF + buf * GSB;
        #pragma unroll
        for (int ks = 0; ks < 4; ks++) {
            uint32_t a[4][4];
            #pragma unroll
            for (int mi = 0; mi < 4; mi++) {
                const float* p = as + (wm + 16 * mi + gq) * 40 + 8 * ks + 2 * qi;
                float2 v0 = *(const float2*)p;            // row r : (k, k+4)
                float2 v1 = *(const float2*)(p + 8 * 40); // row r+8
                a[mi][0] = fbits(v0.x); a[mi][1] = fbits(v1.x);
                a[mi][2] = fbits(v0.y); a[mi][3] = fbits(v1.y);
            }
            #pragma unroll
            for (int nt = 0; nt < 8; nt++) {
                float2 vb = *(const float2*)(bs + (wn + 8 * nt + gq) * 40 + 8 * ks + 2 * qi);
                uint32_t b[2] = { fbits(vb.x), fbits(vb.y) };
                #pragma unroll
                for (int mi = 0; mi < 4; mi++)
                    mma_tf32(C[mi][nt], a[mi], b);
            }
        }
        buf = (buf == 2) ? 0 : buf + 1;
        nbuf = (nbuf == 2) ? 0 : nbuf + 1;
    }
}

// ---------------------------------------------------------------------------
// Kernel 1: fused QKV projection. grid=(4, 32, 3), CTA tile 128x256.
// Q natural; K hd-interleaved; V transposed [hd][s~].
// ---------------------------------------------------------------------------
__global__ __launch_bounds__(256, 1) void qkv_kernel()
{
    extern __shared__ float sm[];
    const int z = blockIdx.z;
    const float* w = (z == 0) ? g_wqc : ((z == 1) ? g_wkc : g_wvc);
    const int m0 = blockIdx.y * 128, n0 = blockIdx.x * 256;

    float C[4][8][4];
    gemm128_core(g_xc + (size_t)m0 * D_DIM, w + (size_t)n0 * D_DIM, C, sm);

    const int tid = threadIdx.x, wid = tid >> 5, lane = tid & 31;
    const int gq = lane >> 2, qi = lane & 3;
    const int wm = (wid >> 2) * 64, wn = (wid & 3) * 64;

    #pragma unroll
    for (int mi = 0; mi < 4; mi++)
        #pragma unroll
        for (int nt = 0; nt < 8; nt++) {
            int m = m0 + wm + 16 * mi + gq;
            int n = n0 + wn + 8 * nt + 2 * qi;
            int h = n >> 6, hd = n & 63, bb = m >> 11, s = m & (S_LEN - 1);
            float v0, v1, v2, v3;
            if (z == 0) {
                v0 = u2f(f2tf(C[mi][nt][0] * 0.125f));
                v1 = u2f(f2tf(C[mi][nt][1] * 0.125f));
                v2 = u2f(f2tf(C[mi][nt][2] * 0.125f));
                v3 = u2f(f2tf(C[mi][nt][3] * 0.125f));
            } else {
                v0 = u2f(f2tf(C[mi][nt][0]));
                v1 = u2f(f2tf(C[mi][nt][1]));
                v2 = u2f(f2tf(C[mi][nt][2]));
                v3 = u2f(f2tf(C[mi][nt][3]));
            }
            if (z == 0) {          // Q natural [s][hd]
                float* p0 = g_q + (((size_t)bb * NH + h) * S_LEN + s) * HDIM + hd;
                float* p1 = g_q + (((size_t)bb * NH + h) * S_LEN + s + 8) * HDIM + hd;
                *(float2*)p0 = make_float2(v0, v1);
                *(float2*)p1 = make_float2(v2, v3);
            } else if (z == 1) {   // K [s][hd~] hd-interleaved
                float* p0 = g_k + (((size_t)bb * NH + h) * S_LEN + s) * HDIM;
                float* p1 = g_k + (((size_t)bb * NH + h) * S_LEN + s + 8) * HDIM;
                int c0 = ilv8(hd), c1 = ilv8(hd + 1);
                p0[c0] = v0; p0[c1] = v1;
                p1[c0] = v2; p1[c1] = v3;
            } else {               // V^T [hd][s~] s-interleaved
                size_t base = ((size_t)bb * NH + h) * HDIM;
                float* r0 = g_v + (base + hd) * S_LEN;
                float* r1 = g_v + (base + hd + 1) * S_LEN;
                int s0 = ilv8(s), s1 = s0 + 8;   // ilv8(s+8) == ilv8(s)+8
                r0[s0] = v0; r1[s0] = v1;
                r0[s1] = v2; r1[s1] = v3;
            }
        }
}

// ---------------------------------------------------------------------------
// Kernel 3: output projection + bias. grid=(4, 32). out natural.
// ---------------------------------------------------------------------------
__global__ __launch_bounds__(256, 1) void oproj_kernel(
    const float* __restrict__ bo, float* __restrict__ out)
{
    extern __shared__ float sm[];
    const int m0 = blockIdx.y * 128, n0 = blockIdx.x * 256;

    float C[4][8][4];
    gemm128_core(g_ctx + (size_t)m0 * D_DIM, g_woc + (size_t)n0 * D_DIM, C, sm);

    const int tid = threadIdx.x, wid = tid >> 5, lane = tid & 31;
    const int gq = lane >> 2, qi = lane & 3;
    const int wm = (wid >> 2) * 64, wn = (wid & 3) * 64;

    #pragma unroll
    for (int mi = 0; mi < 4; mi++)
        #pragma unroll
        for (int nt = 0; nt < 8; nt++) {
            int m = m0 + wm + 16 * mi + gq;
            int n = n0 + wn + 8 * nt + 2 * qi;
            float b0 = __ldg(bo + n), b1 = __ldg(bo + n + 1);
            *(float2*)(out + (size_t)m * D_DIM + n) =
                make_float2(C[mi][nt][0] + b0, C[mi][nt][1] + b1);
            *(float2*)(out + (size_t)(m + 8) * D_DIM + n) =
                make_float2(C[mi][nt][2] + b0, C[mi][nt][3] + b1);
        }
}

// ---------------------------------------------------------------------------
// Kernel 2: flash attention (warp-exclusive softmax, R8 structure).
// K stride 72, V transposed [64][136] — all B-frag loads LDS.64.
// ---------------------------------------------------------------------------
#define KST 9216                        // K stage floats (128*72)
#define VST 8704                        // Vt stage floats (64*136)
#define AV_OFF (2 * KST)
#define ATTN_SMEM ((AV_OFF + 2 * VST) * 4)   // 143360 B

__device__ __forceinline__ void attn_prefetch(
    uint32_t sbase, const float* __restrict__ kp, const float* __restrict__ vtp, int kt)
{
    const int tid = threadIdx.x;
    const int st = kt & 1;
    #pragma unroll
    for (int t = 0; t < 8; t++) {       // K: 128 rows x 64 floats
        int i = tid + t * 256, row = i >> 4, c4 = i & 15;
        cpa16(sbase + (st * KST + row * 72 + c4 * 4) * 4,
              kp + (size_t)(kt * 128 + row) * HDIM + c4 * 4);
    }
    #pragma unroll
    for (int t = 0; t < 8; t++) {       // Vt: 64 rows x 128 floats
        int i = tid + t * 256, row = i >> 5, c8 = i & 31;
        cpa16(sbase + (AV_OFF + st * VST + row * 136 + c8 * 4) * 4,
              vtp + (size_t)row * S_LEN + kt * 128 + c8 * 4);
    }
    cpa_commit();
}

// C-fragment (exp'd scores, 16x8 tile) -> A-fragment for the PV mma.
__device__ __forceinline__ void p_to_afrag(const float c[4], uint32_t a[4], int lane) {
    const int qi = lane & 3;
    const int s0 = (lane & ~3) | (qi >> 1);
    const int s1 = s0 + 2;
    float t0 = __shfl_sync(0xffffffffu, c[0], s0);
    float t1 = __shfl_sync(0xffffffffu, c[1], s0);
    float t2 = __shfl_sync(0xffffffffu, c[2], s0);
    float t3 = __shfl_sync(0xffffffffu, c[3], s0);
    float u0 = __shfl_sync(0xffffffffu, c[0], s1);
    float u1 = __shfl_sync(0xffffffffu, c[1], s1);
    float u2 = __shfl_sync(0xffffffffu, c[2], s1);
    float u3 = __shfl_sync(0xffffffffu, c[3], s1);
    const bool odd = qi & 1;
    a[0] = f2tf(odd ? t1 : t0);
    a[1] = f2tf(odd ? t3 : t2);
    a[2] = f2tf(odd ? u1 : u0);
    a[3] = f2tf(odd ? u3 : u2);
}

__global__ __launch_bounds__(256, 1) void attn_kernel()
{
    extern __shared__ float sm[];
    const uint32_t sbase = smem_u32(sm);

    const int bh = blockIdx.y, qt = blockIdx.x;
    const int tid = threadIdx.x, wid = tid >> 5, lane = tid & 31;
    const int gq = lane >> 2, qi = lane & 3;
    const int wm = wid * 16;

    const float* qp  = g_q + ((size_t)bh * S_LEN + qt * 128) * HDIM;
    const float* kp  = g_k + (size_t)bh * S_LEN * HDIM;
    const float* vtp = g_v + (size_t)bh * HDIM * S_LEN;

    attn_prefetch(sbase, kp, vtp, 0);

    // Q fragments in registers (Q natural, pre-scaled + tf32-rounded)
    uint32_t qa[8][4];
    {
        const float* r0 = qp + (size_t)(wm + gq) * HDIM;
        const float* r1 = qp + (size_t)(wm + 8 + gq) * HDIM;
        #pragma unroll
        for (int ks = 0; ks < 8; ks++) {
            qa[ks][0] = fbits(__ldg(r0 + 8 * ks + qi));
            qa[ks][1] = fbits(__ldg(r1 + 8 * ks + qi));
            qa[ks][2] = fbits(__ldg(r0 + 8 * ks + qi + 4));
            qa[ks][3] = fbits(__ldg(r1 + 8 * ks + qi + 4));
        }
    }

    float O[8][4];
    float m0 = -1e30f, m1 = -1e30f, l0 = 0.f, l1 = 0.f;
    #pragma unroll
    for (int nt = 0; nt < 8; nt++)
        #pragma unroll
        for (int r = 0; r < 4; r++) O[nt][r] = 0.f;

    #pragma unroll 1
    for (int kt = 0; kt < S_LEN / 128; kt++) {
        cpa_wait<0>();
        __syncthreads();
        if (kt + 1 < S_LEN / 128) attn_prefetch(sbase, kp, vtp, kt + 1);

        const float* ks_ = sm + (kt & 1) * KST;
        const float* vs_ = sm + AV_OFF + (kt & 1) * VST;

        // S = Q @ K^T : 16 rows x 128 keys
        float Cs[16][4];
        #pragma unroll
        for (int nt = 0; nt < 16; nt++)
            #pragma unroll
            for (int r = 0; r < 4; r++) Cs[nt][r] = 0.f;

        #pragma unroll
        for (int ksi = 0; ksi < 8; ksi++) {
            #pragma unroll
            for (int nt = 0; nt < 16; nt++) {
                float2 vb = *(const float2*)(ks_ + (8 * nt + gq) * 72 + 8 * ksi + 2 * qi);
                uint32_t b[2] = { fbits(vb.x), fbits(vb.y) };
                mma_tf32(Cs[nt], qa[ksi], b);
            }
        }

        // warp-local online softmax
        float rm0 = Cs[0][0], rm1 = Cs[0][2];
        #pragma unroll
        for (int nt = 0; nt < 16; nt++) {
            rm0 = fmaxf(rm0, fmaxf(Cs[nt][0], Cs[nt][1]));
            rm1 = fmaxf(rm1, fmaxf(Cs[nt][2], Cs[nt][3]));
        }
        rm0 = fmaxf(rm0, __shfl_xor_sync(0xffffffffu, rm0, 1));
        rm0 = fmaxf(rm0, __shfl_xor_sync(0xffffffffu, rm0, 2));
        rm1 = fmaxf(rm1, __shfl_xor_sync(0xffffffffu, rm1, 1));
        rm1 = fmaxf(rm1, __shfl_xor_sync(0xffffffffu, rm1, 2));

        float mn0 = fmaxf(m0, rm0), mn1 = fmaxf(m1, rm1);
        float corr0 = __expf(m0 - mn0), corr1 = __expf(m1 - mn1);
        m0 = mn0; m1 = mn1;

        float ps0 = 0.f, ps1 = 0.f;
        #pragma unroll
        for (int nt = 0; nt < 16; nt++) {
            float e0 = __expf(Cs[nt][0] - mn0), e1 = __expf(Cs[nt][1] - mn0);
            float e2 = __expf(Cs[nt][2] - mn1), e3 = __expf(Cs[nt][3] - mn1);
            Cs[nt][0] = e0; Cs[nt][1] = e1; Cs[nt][2] = e2; Cs[nt][3] = e3;
            ps0 += e0 + e1; ps1 += e2 + e3;
        }
        ps0 += __shfl_xor_sync(0xffffffffu, ps0, 1);
        ps0 += __shfl_xor_sync(0xffffffffu, ps0, 2);
        ps1 += __shfl_xor_sync(0xffffffffu, ps1, 1);
        ps1 += __shfl_xor_sync(0xffffffffu, ps1, 2);
        l0 = l0 * corr0 + ps0;
        l1 = l1 * corr1 + ps1;

        #pragma unroll
        for (int nt = 0; nt < 8; nt++) {
            O[nt][0] *= corr0; O[nt][1] *= corr0;
            O[nt][2] *= corr1; O[nt][3] *= corr1;
        }

        // O += P @ V : Vt[hd][key~], frag pair adjacent -> LDS.64
        #pragma unroll
        for (int kc = 0; kc < 16; kc++) {
            uint32_t a[4];
            p_to_afrag(Cs[kc], a, lane);
            #pragma unroll
            for (int nt = 0; nt < 8; nt++) {
                float2 vb = *(const float2*)(vs_ + (8 * nt + gq) * 136 + 8 * kc + 2 * qi);
                uint32_t b[2] = { fbits(vb.x), fbits(vb.y) };
                mma_tf32(O[nt], a, b);
            }
        }
    }

    // epilogue: normalize + write ctx [b,s,d~] (d-interleaved for oproj A)
    const int b_ = bh >> 4, h = bh & 15;
    const float inv0 = 1.f / l0, inv1 = 1.f / l1;
    const int s = qt * 128 + wm + gq;
    float* p0 = g_ctx + (((size_t)b_ * S_LEN + s) * NH + h) * HDIM;
    float* p1 = g_ctx + (((size_t)b_ * S_LEN + s + 8) * NH + h) * HDIM;
    #pragma unroll
    for (int nt = 0; nt < 8; nt++) {
        int cc = 8 * nt + 2 * qi;
        int c0 = ilv8(cc), c1 = ilv8(cc + 1);
        p0[c0] = u2f(f2tf(O[nt][0] * inv0));
        p0[c1] = u2f(f2tf(O[nt][1] * inv0));
        p1[c0] = u2f(f2tf(O[nt][2] * inv1));
        p1[c1] = u2f(f2tf(O[nt][3] * inv1));
    }
}

// ---------------------------------------------------------------------------
extern "C" void kernel_launch(void* const* d_in, const int* in_sizes, int n_in,
                              void* d_out, int out_size)
{
    const float* x  = (const float*)d_in[0];
    const float* wq = (const float*)d_in[1];
    const float* wk = (const float*)d_in[2];
    const float* wv = (const float*)d_in[3];
    const float* wo = (const float*)d_in[4];
    const float* bo = (const float*)d_in[5];
    float* out = (float*)d_out;

    cudaFuncSetAttribute(qkv_kernel,   cudaFuncAttributeMaxDynamicSharedMemorySize, GEMM_SMEM);
    cudaFuncSetAttribute(oproj_kernel, cudaFuncAttributeMaxDynamicSharedMemorySize, GEMM_SMEM);
    cudaFuncSetAttribute(attn_kernel,  cudaFuncAttributeMaxDynamicSharedMemorySize, ATTN_SMEM);

    prep_kernel<<<dim3(256, 5), 256>>>(x, wq, wk, wv, wo);
    qkv_kernel<<<dim3(D_DIM / 256, M_TOT / 128, 3), 256, GEMM_SMEM>>>();
    attn_kernel<<<dim3(S_LEN / 128, NB * NH), 256, ATTN_SMEM>>>();
    oproj_kernel<<<dim3(D_DIM / 256, M_TOT / 128), 256, GEMM_SMEM>>>(bo, out);
}

// round 10
// speedup vs baseline: 1.0459x; 1.0459x over previous
#include <cuda_runtime.h>
#include <cstdint>

#define S_LEN 2048
#define D_DIM 1024
#define NH    16
#define HDIM  64
#define NB    2
#define M_TOT 4096

// Scratch (all tf32-rounded where consumed by mma) — R8 layouts (natural)
__device__ float g_q[NB * NH * S_LEN * HDIM];   // [b,h,s,hd], 0.125-scaled
__device__ float g_k[NB * NH * S_LEN * HDIM];
__device__ float g_v[NB * NH * S_LEN * HDIM];
__device__ float g_ctx[NB * S_LEN * D_DIM];     // [b,s,d]
__device__ float g_xc[M_TOT * D_DIM];
__device__ float g_wqc[D_DIM * D_DIM];
__device__ float g_wkc[D_DIM * D_DIM];
__device__ float g_wvc[D_DIM * D_DIM];
__device__ float g_woc[D_DIM * D_DIM];

// ---------------------------------------------------------------------------
__device__ __forceinline__ uint32_t f2tf(float f) {
    uint32_t u;
    asm("cvt.rna.tf32.f32 %0, %1;" : "=r"(u) : "f"(f));
    return u;
}
__device__ __forceinline__ float u2f(uint32_t u) { return __uint_as_float(u); }
__device__ __forceinline__ uint32_t fbits(float f) { return __float_as_uint(f); }

__device__ __forceinline__ uint32_t smem_u32(const void* p) {
    uint32_t a;
    asm("{ .reg .u64 t; cvta.to.shared.u64 t, %1; cvt.u32.u64 %0, t; }" : "=r"(a) : "l"(p));
    return a;
}
__device__ __forceinline__ void mma_tf32(float d[4], const uint32_t a[4], const uint32_t b[2]) {
    asm("mma.sync.aligned.m16n8k8.row.col.f32.tf32.tf32.f32 "
        "{%0,%1,%2,%3}, {%4,%5,%6,%7}, {%8,%9}, {%0,%1,%2,%3};"
        : "+f"(d[0]), "+f"(d[1]), "+f"(d[2]), "+f"(d[3])
        : "r"(a[0]), "r"(a[1]), "r"(a[2]), "r"(a[3]), "r"(b[0]), "r"(b[1]));
}
__device__ __forceinline__ void cpa16(uint32_t dst, const void* src) {
    asm volatile("cp.async.ca.shared.global [%0], [%1], 16;" :: "r"(dst), "l"(src) : "memory");
}
__device__ __forceinline__ void cpa_commit() {
    asm volatile("cp.async.commit_group;" ::: "memory");
}
template <int N>
__device__ __forceinline__ void cpa_wait() {
    asm volatile("cp.async.wait_group %0;" :: "n"(N) : "memory");
}

// ---------------------------------------------------------------------------
// Prep: tf32-round x and all weights once (R8 verbatim).
// ---------------------------------------------------------------------------
__global__ __launch_bounds__(256) void prep_kernel(
    const float* __restrict__ x,  const float* __restrict__ wq,
    const float* __restrict__ wk, const float* __restrict__ wv,
    const float* __restrict__ wo)
{
    const float* src; float* dst; int n4;
    switch (blockIdx.y) {
        case 0: src = x;  dst = g_xc;  n4 = M_TOT * D_DIM / 4; break;
        case 1: src = wq; dst = g_wqc; n4 = D_DIM * D_DIM / 4; break;
        case 2: src = wk; dst = g_wkc; n4 = D_DIM * D_DIM / 4; break;
        case 3: src = wv; dst = g_wvc; n4 = D_DIM * D_DIM / 4; break;
        default: src = wo; dst = g_woc; n4 = D_DIM * D_DIM / 4; break;
    }
    const int stride = gridDim.x * blockDim.x;
    for (int i = blockIdx.x * blockDim.x + threadIdx.x; i < n4; i += stride) {
        float4 v = __ldg((const float4*)src + i);
        ((float4*)dst)[i] = make_float4(u2f(f2tf(v.x)), u2f(f2tf(v.y)),
                                        u2f(f2tf(v.z)), u2f(f2tf(v.w)));
    }
}

// ---------------------------------------------------------------------------
// GEMM core v3: D[128,128] = A[128,1024] @ B[128,1024]^T, tf32 pre-rounded.
// 128 thr, 4 warps = 2(m) x 2(n); warp tile 64x64; 2-stage cp.async,
// 1 barrier/chunk (prefetch issued after barrier, lands during compute).
// SMEM 73728 B -> 2 CTAs/SM (two independent barrier domains).
// ---------------------------------------------------------------------------
#define GSA 4608                        // floats per stage (128*36), A and B alike
#define GB_OFF (2 * GSA)
#define GEMM_SMEM (4 * GSA * 4)         // 73728 B

__device__ __forceinline__ void gemm_stage(
    uint32_t sbase, int buf, const float* __restrict__ Ag,
    const float* __restrict__ Bg, int ch)
{
    const int tid = threadIdx.x;
    #pragma unroll
    for (int t = 0; t < 8; t++) {       // A: 128 rows x 32 k
        int i = tid + t * 128, row = i >> 3, c4 = i & 7;
        cpa16(sbase + (buf * GSA + row * 36 + c4 * 4) * 4,
              Ag + (size_t)row * D_DIM + ch * 32 + c4 * 4);
    }
    #pragma unroll
    for (int t = 0; t < 8; t++) {       // B: 128 rows x 32 k
        int i = tid + t * 128, row = i >> 3, c4 = i & 7;
        cpa16(sbase + (GB_OFF + buf * GSA + row * 36 + c4 * 4) * 4,
              Bg + (size_t)row * D_DIM + ch * 32 + c4 * 4);
    }
    cpa_commit();
}

__device__ __forceinline__ void gemm128_core(
    const float* __restrict__ Ag, const float* __restrict__ Bg,
    float C[4][8][4], float* sm)
{
    const uint32_t sbase = smem_u32(sm);
    const int tid = threadIdx.x, wid = tid >> 5, lane = tid & 31;
    const int gq = lane >> 2, qi = lane & 3;
    const int wm = (wid >> 1) * 64, wn = (wid & 1) * 64;

    #pragma unroll
    for (int mi = 0; mi < 4; mi++)
        #pragma unroll
        for (int nt = 0; nt < 8; nt++)
            #pragma unroll
            for (int r = 0; r < 4; r++) C[mi][nt][r] = 0.f;

    gemm_stage(sbase, 0, Ag, Bg, 0);

    #pragma unroll 1
    for (int ch = 0; ch < 32; ch++) {
        cpa_wait<0>();
        __syncthreads();                 // stage ch visible; prev compute done
        if (ch + 1 < 32) gemm_stage(sbase, (ch + 1) & 1, Ag, Bg, ch + 1);

        const float* as = sm + (ch & 1) * GSA;
        const float* bs = sm + GB_OFF + (ch & 1) * GSA;
        #pragma unroll
        for (int ks = 0; ks < 4; ks++) {
            uint32_t a[4][4];
            #pragma unroll
            for (int mi = 0; mi < 4; mi++) {
                const float* p = as + (wm + 16 * mi + gq) * 36 + 8 * ks + qi;
                a[mi][0] = fbits(p[0]);
                a[mi][1] = fbits(p[8 * 36]);
                a[mi][2] = fbits(p[4]);
                a[mi][3] = fbits(p[8 * 36 + 4]);
            }
            #pragma unroll
            for (int nt = 0; nt < 8; nt++) {
                const float* p = bs + (wn + 8 * nt + gq) * 36 + 8 * ks + qi;
                uint32_t b[2] = { fbits(p[0]), fbits(p[4]) };
                #pragma unroll
                for (int mi = 0; mi < 4; mi++)
                    mma_tf32(C[mi][nt], a[mi], b);
            }
        }
    }
}

// ---------------------------------------------------------------------------
// Kernel 1: fused QKV projection. grid=(8, 32, 3), CTA tile 128x128.
// ---------------------------------------------------------------------------
__global__ __launch_bounds__(128, 2) void qkv_kernel()
{
    extern __shared__ float sm[];
    const int z = blockIdx.z;
    const float* w = (z == 0) ? g_wqc : ((z == 1) ? g_wkc : g_wvc);
    const int m0 = blockIdx.y * 128, n0 = blockIdx.x * 128;

    float C[4][8][4];
    gemm128_core(g_xc + (size_t)m0 * D_DIM, w + (size_t)n0 * D_DIM, C, sm);

    float* dst = (z == 0) ? g_q : ((z == 1) ? g_k : g_v);
    const float scale = (z == 0) ? 0.125f : 1.0f;

    const int tid = threadIdx.x, wid = tid >> 5, lane = tid & 31;
    const int gq = lane >> 2, qi = lane & 3;
    const int wm = (wid >> 1) * 64, wn = (wid & 1) * 64;

    #pragma unroll
    for (int mi = 0; mi < 4; mi++)
        #pragma unroll
        for (int nt = 0; nt < 8; nt++) {
            int m = m0 + wm + 16 * mi + gq;
            int n = n0 + wn + 8 * nt + 2 * qi;
            int h = n >> 6, hd = n & 63, bb = m >> 11, s = m & (S_LEN - 1);
            float* p0 = dst + (((size_t)bb * NH + h) * S_LEN + s) * HDIM + hd;
            float* p1 = dst + (((size_t)bb * NH + h) * S_LEN + s + 8) * HDIM + hd;
            *(float2*)p0 = make_float2(u2f(f2tf(C[mi][nt][0] * scale)),
                                       u2f(f2tf(C[mi][nt][1] * scale)));
            *(float2*)p1 = make_float2(u2f(f2tf(C[mi][nt][2] * scale)),
                                       u2f(f2tf(C[mi][nt][3] * scale)));
        }
}

// ---------------------------------------------------------------------------
// Kernel 3: output projection + bias. grid=(8, 32)
// ---------------------------------------------------------------------------
__global__ __launch_bounds__(128, 2) void oproj_kernel(
    const float* __restrict__ bo, float* __restrict__ out)
{
    extern __shared__ float sm[];
    const int m0 = blockIdx.y * 128, n0 = blockIdx.x * 128;

    float C[4][8][4];
    gemm128_core(g_ctx + (size_t)m0 * D_DIM, g_woc + (size_t)n0 * D_DIM, C, sm);

    const int tid = threadIdx.x, wid = tid >> 5, lane = tid & 31;
    const int gq = lane >> 2, qi = lane & 3;
    const int wm = (wid >> 1) * 64, wn = (wid & 1) * 64;

    #pragma unroll
    for (int mi = 0; mi < 4; mi++)
        #pragma unroll
        for (int nt = 0; nt < 8; nt++) {
            int m = m0 + wm + 16 * mi + gq;
            int n = n0 + wn + 8 * nt + 2 * qi;
            float b0 = __ldg(bo + n), b1 = __ldg(bo + n + 1);
            *(float2*)(out + (size_t)m * D_DIM + n) =
                make_float2(C[mi][nt][0] + b0, C[mi][nt][1] + b1);
            *(float2*)(out + (size_t)(m + 8) * D_DIM + n) =
                make_float2(C[mi][nt][2] + b0, C[mi][nt][3] + b1);
        }
}

// ---------------------------------------------------------------------------
// Kernel 2: flash attention — R8 verbatim (warp-exclusive softmax, 498us best).
// ---------------------------------------------------------------------------
#define AV_OFF (2 * 8704)
#define ATTN_SMEM ((AV_OFF + 2 * 9216) * 4)     // 143360 B

__device__ __forceinline__ void attn_prefetch(
    uint32_t sbase, const float* __restrict__ kp, const float* __restrict__ vp, int kt)
{
    const int tid = threadIdx.x;
    const int st = kt & 1;
    #pragma unroll
    for (int t = 0; t < 8; t++) {
        int i = tid + t * 256, row = i >> 4, c4 = i & 15;
        cpa16(sbase + (st * 8704 + row * 68 + c4 * 4) * 4,
              kp + (size_t)(kt * 128 + row) * HDIM + c4 * 4);
    }
    #pragma unroll
    for (int t = 0; t < 8; t++) {
        int i = tid + t * 256, row = i >> 4, c4 = i & 15;
        cpa16(sbase + (AV_OFF + st * 9216 + row * 72 + c4 * 4) * 4,
              vp + (size_t)(kt * 128 + row) * HDIM + c4 * 4);
    }
    cpa_commit();
}

__device__ __forceinline__ void p_to_afrag(const float c[4], uint32_t a[4], int lane) {
    const int qi = lane & 3;
    const int s0 = (lane & ~3) | (qi >> 1);
    const int s1 = s0 + 2;
    float t0 = __shfl_sync(0xffffffffu, c[0], s0);
    float t1 = __shfl_sync(0xffffffffu, c[1], s0);
    float t2 = __shfl_sync(0xffffffffu, c[2], s0);
    float t3 = __shfl_sync(0xffffffffu, c[3], s0);
    float u0 = __shfl_sync(0xffffffffu, c[0], s1);
    float u1 = __shfl_sync(0xffffffffu, c[1], s1);
    float u2 = __shfl_sync(0xffffffffu, c[2], s1);
    float u3 = __shfl_sync(0xffffffffu, c[3], s1);
    const bool odd = qi & 1;
    a[0] = f2tf(odd ? t1 : t0);
    a[1] = f2tf(odd ? t3 : t2);
    a[2] = f2tf(odd ? u1 : u0);
    a[3] = f2tf(odd ? u3 : u2);
}

__global__ __launch_bounds__(256, 1) void attn_kernel()
{
    extern __shared__ float sm[];
    const uint32_t sbase = smem_u32(sm);

    const int bh = blockIdx.y, qt = blockIdx.x;
    const int tid = threadIdx.x, wid = tid >> 5, lane = tid & 31;
    const int gq = lane >> 2, qi = lane & 3;
    const int wm = wid * 16;

    const float* qp = g_q + ((size_t)bh * S_LEN + qt * 128) * HDIM;
    const float* kp = g_k + (size_t)bh * S_LEN * HDIM;
    const float* vp = g_v + (size_t)bh * S_LEN * HDIM;

    attn_prefetch(sbase, kp, vp, 0);

    uint32_t qa[8][4];
    {
        const float* r0 = qp + (size_t)(wm + gq) * HDIM;
        const float* r1 = qp + (size_t)(wm + 8 + gq) * HDIM;
        #pragma unroll
        for (int ks = 0; ks < 8; ks++) {
            qa[ks][0] = fbits(__ldg(r0 + 8 * ks + qi));
            qa[ks][1] = fbits(__ldg(r1 + 8 * ks + qi));
            qa[ks][2] = fbits(__ldg(r0 + 8 * ks + qi + 4));
            qa[ks][3] = fbits(__ldg(r1 + 8 * ks + qi + 4));
        }
    }

    float O[8][4];
    float m0 = -1e30f, m1 = -1e30f, l0 = 0.f, l1 = 0.f;
    #pragma unroll
    for (int nt = 0; nt < 8; nt++)
        #pragma unroll
        for (int r = 0; r < 4; r++) O[nt][r] = 0.f;

    #pragma unroll 1
    for (int kt = 0; kt < S_LEN / 128; kt++) {
        cpa_wait<0>();
        __syncthreads();
        if (kt + 1 < S_LEN / 128) attn_prefetch(sbase, kp, vp, kt + 1);

        const float* ks_ = sm + (kt & 1) * 8704;
        const float* vs_ = sm + AV_OFF + (kt & 1) * 9216;

        float Cs[16][4];
        #pragma unroll
        for (int nt = 0; nt < 16; nt++)
            #pragma unroll
            for (int r = 0; r < 4; r++) Cs[nt][r] = 0.f;

        #pragma unroll
        for (int ksi = 0; ksi < 8; ksi++) {
            #pragma unroll
            for (int nt = 0; nt < 16; nt++) {
                const float* pb = ks_ + (8 * nt + gq) * 68 + 8 * ksi + qi;
                uint32_t b[2] = { fbits(pb[0]), fbits(pb[4]) };
                mma_tf32(Cs[nt], qa[ksi], b);
            }
        }

        float rm0 = Cs[0][0], rm1 = Cs[0][2];
        #pragma unroll
        for (int nt = 0; nt < 16; nt++) {
            rm0 = fmaxf(rm0, fmaxf(Cs[nt][0], Cs[nt][1]));
            rm1 = fmaxf(rm1, fmaxf(Cs[nt][2], Cs[nt][3]));
        }
        rm0 = fmaxf(rm0, __shfl_xor_sync(0xffffffffu, rm0, 1));
        rm0 = fmaxf(rm0, __shfl_xor_sync(0xffffffffu, rm0, 2));
        rm1 = fmaxf(rm1, __shfl_xor_sync(0xffffffffu, rm1, 1));
        rm1 = fmaxf(rm1, __shfl_xor_sync(0xffffffffu, rm1, 2));

        float mn0 = fmaxf(m0, rm0), mn1 = fmaxf(m1, rm1);
        float corr0 = __expf(m0 - mn0), corr1 = __expf(m1 - mn1);
        m0 = mn0; m1 = mn1;

        float ps0 = 0.f, ps1 = 0.f;
        #pragma unroll
        for (int nt = 0; nt < 16; nt++) {
            float e0 = __expf(Cs[nt][0] - mn0), e1 = __expf(Cs[nt][1] - mn0);
            float e2 = __expf(Cs[nt][2] - mn1), e3 = __expf(Cs[nt][3] - mn1);
            Cs[nt][0] = e0; Cs[nt][1] = e1; Cs[nt][2] = e2; Cs[nt][3] = e3;
            ps0 += e0 + e1; ps1 += e2 + e3;
        }
        ps0 += __shfl_xor_sync(0xffffffffu, ps0, 1);
        ps0 += __shfl_xor_sync(0xffffffffu, ps0, 2);
        ps1 += __shfl_xor_sync(0xffffffffu, ps1, 1);
        ps1 += __shfl_xor_sync(0xffffffffu, ps1, 2);
        l0 = l0 * corr0 + ps0;
        l1 = l1 * corr1 + ps1;

        #pragma unroll
        for (int nt = 0; nt < 8; nt++) {
            O[nt][0] *= corr0; O[nt][1] *= corr0;
            O[nt][2] *= corr1; O[nt][3] *= corr1;
        }

        #pragma unroll
        for (int kc = 0; kc < 16; kc++) {
            uint32_t a[4];
            p_to_afrag(Cs[kc], a, lane);
            const float* pv = vs_ + (size_t)(8 * kc + qi) * 72 + gq;
            #pragma unroll
            for (int nt = 0; nt < 8; nt++) {
                uint32_t b[2] = { fbits(pv[8 * nt]), fbits(pv[4 * 72 + 8 * nt]) };
                mma_tf32(O[nt], a, b);
            }
        }
    }

    const int b_ = bh >> 4, h = bh & 15;
    const float inv0 = 1.f / l0, inv1 = 1.f / l1;
    const int s = qt * 128 + wm + gq;
    #pragma unroll
    for (int nt = 0; nt < 8; nt++) {
        int cc = 8 * nt + 2 * qi;
        float* p0 = g_ctx + (((size_t)b_ * S_LEN + s) * NH + h) * HDIM + cc;
        float* p1 = g_ctx + (((size_t)b_ * S_LEN + s + 8) * NH + h) * HDIM + cc;
        *(float2*)p0 = make_float2(u2f(f2tf(O[nt][0] * inv0)),
                                   u2f(f2tf(O[nt][1] * inv0)));
        *(float2*)p1 = make_float2(u2f(f2tf(O[nt][2] * inv1)),
                                   u2f(f2tf(O[nt][3] * inv1)));
    }
}

// ---------------------------------------------------------------------------
extern "C" void kernel_launch(void* const* d_in, const int* in_sizes, int n_in,
                              void* d_out, int out_size)
{
    const float* x  = (const float*)d_in[0];
    const float* wq = (const float*)d_in[1];
    const float* wk = (const float*)d_in[2];
    const float* wv = (const float*)d_in[3];
    const float* wo = (const float*)d_in[4];
    const float* bo = (const float*)d_in[5];
    float* out = (float*)d_out;

    cudaFuncSetAttribute(qkv_kernel,   cudaFuncAttributeMaxDynamicSharedMemorySize, GEMM_SMEM);
    cudaFuncSetAttribute(oproj_kernel, cudaFuncAttributeMaxDynamicSharedMemorySize, GEMM_SMEM);
    cudaFuncSetAttribute(attn_kernel,  cudaFuncAttributeMaxDynamicSharedMemorySize, ATTN_SMEM);

    prep_kernel<<<dim3(256, 5), 256>>>(x, wq, wk, wv, wo);
    qkv_kernel<<<dim3(D_DIM / 128, M_TOT / 128, 3), 128, GEMM_SMEM>>>();
    attn_kernel<<<dim3(S_LEN / 128, NB * NH), 256, ATTN_SMEM>>>();
    oproj_kernel<<<dim3(D_DIM / 128, M_TOT / 128), 128, GEMM_SMEM>>>(bo, out);
}